// round 11
// baseline (speedup 1.0000x reference)
#include <cuda_runtime.h>
#include <cuda_fp16.h>
#include <math.h>
#include <stdint.h>

#define NP 16384
#define NR 8192
#define GRIDN 13
#define NCELL (GRIDN*GRIDN*GRIDN)
#define CAP 64
#define RADIUS2 (0.075f*0.075f)

// ---------------- static scratch ----------------
__device__ int    d_cellCnt[NCELL];
__device__ float4 d_cellPts[NCELL*CAP];
__device__ int    d_nbr[NP*3];
__device__ unsigned short d_rgbt[NR*128];     // rgb features point-major fp16
__device__ unsigned short d_u[(size_t)NR*1152]; // precomputed W0/W1/W2 . rgb_f
__device__ unsigned short d_hw[382976];       // all weights fp16, k-major
__device__ float  d_bns[5*384];
__device__ float  d_bnt[5*384];

// ---------------- PTX helpers ----------------
__device__ __forceinline__ uint32_t smem_u32(const void* p) {
    uint32_t a;
    asm("{ .reg .u64 t; cvta.to.shared.u64 t, %1; cvt.u32.u64 %0, t; }" : "=r"(a) : "l"(p));
    return a;
}
__device__ __forceinline__ void cpasync16(uint32_t s, const void* g) {
    asm volatile("cp.async.cg.shared.global [%0], [%1], 16;" :: "r"(s), "l"(g));
}
#define CP_COMMIT() asm volatile("cp.async.commit_group;")
#define LDSM4(r0,r1,r2,r3,a) \
    asm volatile("ldmatrix.sync.aligned.m8n8.x4.shared.b16 {%0,%1,%2,%3},[%4];" \
        : "=r"(r0),"=r"(r1),"=r"(r2),"=r"(r3) : "r"(a))
#define LDSM4T(r0,r1,r2,r3,a) \
    asm volatile("ldmatrix.sync.aligned.m8n8.x4.trans.shared.b16 {%0,%1,%2,%3},[%4];" \
        : "=r"(r0),"=r"(r1),"=r"(r2),"=r"(r3) : "r"(a))
__device__ __forceinline__ void mma16(float* c, const uint32_t* a, uint32_t b0, uint32_t b1) {
    asm volatile(
        "mma.sync.aligned.m16n8k16.row.col.f32.f16.f16.f32 "
        "{%0,%1,%2,%3},{%4,%5,%6,%7},{%8,%9},{%0,%1,%2,%3};"
        : "+f"(c[0]), "+f"(c[1]), "+f"(c[2]), "+f"(c[3])
        : "r"(a[0]), "r"(a[1]), "r"(a[2]), "r"(a[3]), "r"(b0), "r"(b1));
}

// ---------------- spatial grid + 3NN ----------------
__global__ void k_clear() {
    int i = blockIdx.x*blockDim.x + threadIdx.x;
    if (i < NCELL) d_cellCnt[i] = 0;
}
__device__ __forceinline__ int cidx(float v) {
    int c = (int)(v * (float)GRIDN);
    return c < 0 ? 0 : (c > GRIDN-1 ? GRIDN-1 : c);
}
__global__ void k_build(const float* __restrict__ rgb) {
    int i = blockIdx.x*blockDim.x + threadIdx.x;
    if (i >= NR) return;
    float x = rgb[3*i], y = rgb[3*i+1], z = rgb[3*i+2];
    int c = (cidx(x)*GRIDN + cidx(y))*GRIDN + cidx(z);
    int p = atomicAdd(&d_cellCnt[c], 1);
    if (p < CAP) d_cellPts[c*CAP + p] = make_float4(x, y, z, __int_as_float(i));
}
__global__ void k_3nn(const float* __restrict__ pcd) {
    int i = blockIdx.x*blockDim.x + threadIdx.x;
    if (i >= NP) return;
    float x = pcd[3*i], y = pcd[3*i+1], z = pcd[3*i+2];
    int cx = cidx(x), cy = cidx(y), cz = cidx(z);
    int x0 = max(cx-1,0), x1 = min(cx+1,GRIDN-1);
    int y0 = max(cy-1,0), y1 = min(cy+1,GRIDN-1);
    int z0 = max(cz-1,0), z1 = min(cz+1,GRIDN-1);
    float b0 = 3.4e38f, b1 = 3.4e38f, b2 = 3.4e38f;
    int   i0 = NR, i1 = NR, i2 = NR;
    for (int ax = x0; ax <= x1; ax++)
    for (int ay = y0; ay <= y1; ay++)
    for (int az = z0; az <= z1; az++) {
        int c = (ax*GRIDN + ay)*GRIDN + az;
        int cnt = min(d_cellCnt[c], CAP);
        const float4* pts = &d_cellPts[c*CAP];
        for (int p = 0; p < cnt; p++) {
            float4 q = pts[p];
            float dx = x - q.x, dy = y - q.y, dz = z - q.z;
            float d = fmaf(dx, dx, fmaf(dy, dy, dz*dz));
            if (d <= RADIUS2 && d < b2) {
                int qi = __float_as_int(q.w);
                if (d < b0)      { b2=b1;i2=i1; b1=b0;i1=i0; b0=d;i0=qi; }
                else if (d < b1) { b2=b1;i2=i1; b1=d; i1=qi; }
                else             { b2=d; i2=qi; }
            }
        }
    }
    d_nbr[3*i] = i0; d_nbr[3*i+1] = i1; d_nbr[3*i+2] = i2;
}

// ---------------- rgb features: ch-major fp32 -> point-major fp16 ----------------
__global__ void k_trans16(const float* __restrict__ in) {
    __shared__ float t[32][33];
    int nb = blockIdx.x * 32;
    int cb = blockIdx.y * 32;
    int tx = threadIdx.x, ty = threadIdx.y;
    #pragma unroll
    for (int i = 0; i < 32; i += 8)
        t[ty+i][tx] = in[(size_t)(cb + ty + i)*NR + nb + tx];
    __syncthreads();
    #pragma unroll
    for (int i = 0; i < 32; i += 8)
        d_rgbt[(size_t)(nb + ty + i)*128 + cb + tx] =
            __half_as_ushort(__float2half(t[tx][ty+i]));
}

// ---------------- fold BN ----------------
__global__ void k_bnprep5(const float* b0, const float* b1, const float* b2,
                          const float* b3, const float* b4) {
    const int Cs[5] = {384, 256, 160, 160, 128};
    const float* ps[5] = {b0, b1, b2, b3, b4};
    int slot = blockIdx.x;
    const float* bn = ps[slot];
    int C = Cs[slot];
    for (int c = threadIdx.x; c < C; c += blockDim.x) {
        float g = bn[c], b = bn[C+c], m = bn[2*C+c], v = bn[3*C+c];
        float s = g * rsqrtf(v + 1e-5f);
        d_bns[slot*384 + c] = s;
        d_bnt[slot*384 + c] = b - m*s;
    }
}

// ------ weight convert: fp32 [M][K] (strided src) -> fp16 k-major [K][dstM] ------
struct WSegG {
    const float* s[10];
    int M[10], K[10], off[10], dstM[10], dstOff[10], srcLd[10], srcCoff[10];
};
__global__ void k_wcvt(WSegG ws) {
    int t = blockIdx.x*blockDim.x + threadIdx.x;
    #pragma unroll
    for (int i = 0; i < 10; i++) {
        int sz = ws.M[i] * ws.K[i];
        if (t < sz) {
            int m = t / ws.K[i], kk = t % ws.K[i];
            d_hw[ws.off[i] + (size_t)kk * ws.dstM[i] + ws.dstOff[i] + m] =
                __half_as_ushort(__float2half(ws.s[i][(size_t)m*ws.srcLd[i] + ws.srcCoff[i] + kk]));
            return;
        }
        t -= sz;
    }
}

// ---------------- u-GEMM: d_u[j][m] = W_big[m,:] . rgb_f[j,:]  (no bias) ----------------
// 128 pts x 128 out per CTA, K=128, BK=64 double-buffered cp.async. M=1152, Cout=1152.
#define UG_ASTR 72
#define UG_ABYTES (128*UG_ASTR*2)
#define UG_STAGE  (UG_ABYTES + 64*136*2)
__global__ void __launch_bounds__(256, 2)
k_ug(const __half* __restrict__ X, const __half* __restrict__ W16, __half* __restrict__ Y)
{
    extern __shared__ __align__(16) unsigned char smem[];
    uint32_t sbase = smem_u32(smem);
    const int tid = threadIdx.x;
    const int wid = tid >> 5, lane = tid & 31;
    const int warp_m = wid & 3, warp_n = wid >> 2;
    const int by = blockIdx.y;
    const size_t rowbase = (size_t)blockIdx.x * 128;
    const int li = lane & 15, h8 = (lane >> 4) << 3;

    float acc[2][8][4];
    #pragma unroll
    for (int i = 0; i < 2; i++)
        #pragma unroll
        for (int j = 0; j < 8; j++)
            #pragma unroll
            for (int q = 0; q < 4; q++) acc[i][j][q] = 0.f;

    auto issue = [&](int c, int s) {
        int k0 = c << 6;
        uint32_t As = sbase + s*UG_STAGE;
        uint32_t Bs = As + UG_ABYTES;
        #pragma unroll
        for (int i = 0; i < 4; i++) {
            int idx = tid + i*256;
            int r = idx >> 3, q = idx & 7;
            cpasync16(As + (r*UG_ASTR + q*8)*2, X + (rowbase + r)*128 + k0 + q*8);
        }
        #pragma unroll
        for (int i = 0; i < 4; i++) {
            int idx = tid + i*256;
            int kr = idx >> 4, qn = idx & 15;
            cpasync16(Bs + (kr*136 + qn*8)*2, W16 + (size_t)(k0 + kr)*1152 + by*128 + qn*8);
        }
        CP_COMMIT();
    };

    issue(0, 0);
    issue(1, 1);
    for (int c = 0; c < 2; c++) {
        if (c == 0) asm volatile("cp.async.wait_group 1;");
        else        asm volatile("cp.async.wait_group 0;");
        __syncthreads();
        uint32_t As = sbase + c*UG_STAGE;
        uint32_t Bs = As + UG_ABYTES;
        #pragma unroll
        for (int kk = 0; kk < 64; kk += 16) {
            uint32_t a[2][4];
            #pragma unroll
            for (int mt = 0; mt < 2; mt++) {
                uint32_t ad = As + (((warp_m*32 + mt*16 + li)*UG_ASTR) + kk + h8)*2;
                LDSM4(a[mt][0], a[mt][1], a[mt][2], a[mt][3], ad);
            }
            uint32_t b[4][4];
            #pragma unroll
            for (int nt2 = 0; nt2 < 4; nt2++) {
                uint32_t bd = Bs + ((kk + li)*136 + warp_n*64 + nt2*16 + h8)*2;
                LDSM4T(b[nt2][0], b[nt2][1], b[nt2][2], b[nt2][3], bd);
            }
            #pragma unroll
            for (int mt = 0; mt < 2; mt++)
                #pragma unroll
                for (int nt = 0; nt < 8; nt++)
                    mma16(acc[mt][nt], a[mt], b[nt>>1][(nt&1)*2], b[nt>>1][(nt&1)*2+1]);
        }
        __syncthreads();
    }

    const int g = lane >> 2, tp = (lane & 3) * 2;
    #pragma unroll
    for (int nt = 0; nt < 8; nt++) {
        int m = by*128 + warp_n*64 + nt*8 + tp;
        #pragma unroll
        for (int mt = 0; mt < 2; mt++) {
            #pragma unroll
            for (int h = 0; h < 2; h++) {
                int pt = (int)rowbase + warp_m*32 + mt*16 + h*8 + g;
                *(__half2*)&Y[(size_t)pt*1152 + m] =
                    __floats2half2_rn(acc[mt][nt][2*h], acc[mt][nt][2*h+1]);
            }
        }
    }
}

// ---------------- mega kernel: h1 assembly + 7-layer chain + heads ----------------
#define ASTR2 392
#define ABYTES2 (64*ASTR2*2)          // 50176
#define BSTR2 264
#define BBYTES2 (64*BSTR2*2)          // 33792
#define WSTR 136
#define WCH (32*WSTR*2)               // 8704
#define SMEM2 (ABYTES2 + BBYTES2 + 3*WCH)  // 110080

struct LBias { const float* b[7]; };

__global__ void __launch_bounds__(256, 2)
k_mega(const float* __restrict__ pcdf, const __half* __restrict__ Wg, LBias bias,
       const float* __restrict__ cc1b,
       const float* __restrict__ sh2w, const float* __restrict__ sh2b,
       float* __restrict__ outScore, float* __restrict__ outVf)
{
    extern __shared__ __align__(16) unsigned char smem[];
    const uint32_t sbase = smem_u32(smem);
    const int tid = threadIdx.x, wid = tid >> 5, lane = tid & 31;
    const int warp_m = wid & 3, warp_n = wid >> 2;   // 4 x 2 warps, warp = 16 pts x 64 ch
    const int li = lane & 15, h8 = (lane >> 4) << 3;
    const int rowbase = blockIdx.x * 64;
    unsigned char* Abuf = smem;
    unsigned char* Bbuf = smem + ABYTES2;
    const uint32_t Wb = sbase + ABYTES2 + BBYTES2;

    // ---- maxf gather -> B cols 128..255 (8 pts per warp) ----
    #pragma unroll
    for (int i = 0; i < 8; i++) {
        int p = wid*8 + i;
        int ptg = rowbase + p;
        int n0 = d_nbr[3*ptg], n1 = d_nbr[3*ptg+1], n2 = d_nbr[3*ptg+2];
        uint2 z = make_uint2(0u, 0u);
        uint2 u0 = (n0 < NR) ? *(const uint2*)&d_rgbt[(size_t)n0*128 + lane*4] : z;
        uint2 u1 = (n1 < NR) ? *(const uint2*)&d_rgbt[(size_t)n1*128 + lane*4] : z;
        uint2 u2 = (n2 < NR) ? *(const uint2*)&d_rgbt[(size_t)n2*128 + lane*4] : z;
        __half2 a0 = *(__half2*)&u0.x, a1 = *(__half2*)&u0.y;
        __half2 b0 = *(__half2*)&u1.x, b1 = *(__half2*)&u1.y;
        __half2 c0 = *(__half2*)&u2.x, c1 = *(__half2*)&u2.y;
        __half2 m0 = __hmax2(__hmax2(a0, b0), c0);
        __half2 m1 = __hmax2(__hmax2(a1, b1), c1);
        uint2 mu; mu.x = *(uint32_t*)&m0; mu.y = *(uint32_t*)&m1;
        *(uint2*)(Bbuf + (size_t)(p*BSTR2 + 128 + lane*4)*2) = mu;
    }

    // ---- h1 assembly: A cols 0..383 = relu(bn0(u0[n0]+u1[n1]+u2[n2] + cc1_b)) ----
    {
        int pt = tid >> 2, tq = tid & 3;
        int ptg = rowbase + pt;
        int n0 = d_nbr[3*ptg], n1 = d_nbr[3*ptg+1], n2 = d_nbr[3*ptg+2];
        const unsigned short* u0p = (n0 < NR) ? &d_u[(size_t)n0*1152]       : nullptr;
        const unsigned short* u1p = (n1 < NR) ? &d_u[(size_t)n1*1152 + 384] : nullptr;
        const unsigned short* u2p = (n2 < NR) ? &d_u[(size_t)n2*1152 + 768] : nullptr;
        for (int c = tq*96; c < tq*96 + 96; c += 8) {
            float f[8] = {0,0,0,0,0,0,0,0};
            #pragma unroll
            for (int k = 0; k < 3; k++) {
                const unsigned short* up = (k==0) ? u0p : (k==1) ? u1p : u2p;
                if (up) {
                    uint4 v = *(const uint4*)(up + c);
                    const __half2* hv = (const __half2*)&v;
                    #pragma unroll
                    for (int j = 0; j < 4; j++) {
                        f[2*j]   += __low2float(hv[j]);
                        f[2*j+1] += __high2float(hv[j]);
                    }
                }
            }
            uint4 o;
            __half2* ho = (__half2*)&o;
            #pragma unroll
            for (int j = 0; j < 4; j++) {
                int c0i = c + 2*j, c1i = c + 2*j + 1;
                float x0 = fmaf(f[2*j]   + __ldg(&cc1b[c0i]), __ldg(&d_bns[c0i]), __ldg(&d_bnt[c0i]));
                float x1 = fmaf(f[2*j+1] + __ldg(&cc1b[c1i]), __ldg(&d_bns[c1i]), __ldg(&d_bnt[c1i]));
                ho[j] = __floats2half2_rn(fmaxf(x0, 0.f), fmaxf(x1, 0.f));
            }
            *(uint4*)(Abuf + (size_t)(pt*ASTR2 + c)*2) = o;
        }
    }
    __syncthreads();

    // layer tables (l = 0..6 == cc2, co1, co2, dh1, dh2, dh3, sh1)
    const int Ks[7]   = {384,256,256,160,160,160,128};
    const int Ms[7]   = {128,256,128,160,160,128,128};
    const int dco[7]  = {0,0,32,0,0,0,0};
    const int slot[7] = {-1,1,-1,2,3,-1,4};
    const int woff[7] = {147456,196608,262144,294912,320512,346112,366592};

    for (int l = 0; l < 7; l++) {
        if (l == 2) {   // pcd features -> B cols 0..31 (cc2 output already consumed by co1)
            for (int t = tid; t < 2048; t += 256) {
                int ch = t >> 6, ptl = t & 63;
                ((__half*)Bbuf)[ptl*BSTR2 + ch] =
                    __float2half(pcdf[(size_t)ch*NP + rowbase + ptl]);
            }
            __syncthreads();
        }
        // src: l even -> A (stride 392); l odd -> B (stride 264). dst opposite.
        const int sstr = (l & 1) ? BSTR2 : ASTR2;
        const int dstr = (l & 1) ? ASTR2 : BSTR2;
        const uint32_t srcA = sbase + ((l & 1) ? ABYTES2 : 0);
        unsigned char* dstP = (l & 1) ? Abuf : Bbuf;
        const int K = Ks[l], M = Ms[l];
        const int NKC = K >> 5;
        const __half* W = Wg + woff[l];
        const float* bi = bias.b[l];
        const int sl = slot[l];

        for (int mc = 0; mc < M; mc += 128) {
            const int ncols = min(128, M - mc);
            const int nf = ncols >> 3;
            float acc[8][4];
            #pragma unroll
            for (int j = 0; j < 8; j++)
                #pragma unroll
                for (int q = 0; q < 4; q++) acc[j][q] = 0.f;

            auto issueW = [&](int c) {
                uint32_t stg = Wb + (c % 3) * WCH;
                int tot = 32 * nf;
                for (int t = tid; t < tot; t += 256) {
                    int kr = t / nf, qn = t % nf;
                    cpasync16(stg + (kr*WSTR + qn*8)*2,
                              W + (size_t)(c*32 + kr)*M + mc + qn*8);
                }
                CP_COMMIT();
            };

            int issued = 1;
            issueW(0);
            if (NKC > 1) { issueW(1); issued = 2; }

            for (int c = 0; c < NKC; c++) {
                if (issued < NKC) { issueW(issued); issued++; }
                int pending = issued - c - 1;
                if (pending >= 2)      asm volatile("cp.async.wait_group 2;");
                else if (pending == 1) asm volatile("cp.async.wait_group 1;");
                else                   asm volatile("cp.async.wait_group 0;");
                __syncthreads();
                uint32_t Ws = Wb + (c % 3) * WCH;
                #pragma unroll
                for (int kk = 0; kk < 32; kk += 16) {
                    uint32_t a[4];
                    {
                        uint32_t ad = srcA +
                            ((uint32_t)(warp_m*16 + li)*sstr + c*32 + kk + h8)*2;
                        LDSM4(a[0], a[1], a[2], a[3], ad);
                    }
                    uint32_t b[4][4];
                    #pragma unroll
                    for (int nt2 = 0; nt2 < 4; nt2++) {
                        uint32_t bd = Ws + ((kk + li)*WSTR + warp_n*64 + nt2*16 + h8)*2;
                        LDSM4T(b[nt2][0], b[nt2][1], b[nt2][2], b[nt2][3], bd);
                    }
                    #pragma unroll
                    for (int nt = 0; nt < 8; nt++)
                        mma16(acc[nt], a, b[nt>>1][(nt&1)*2], b[nt>>1][(nt&1)*2+1]);
                }
                __syncthreads();
            }

            // epilogue -> dst SMEM buffer (warp tile 16 pts x 64 ch)
            const int g = lane >> 2, tp = (lane & 3) * 2;
            #pragma unroll
            for (int nt = 0; nt < 8; nt++) {
                int lc = warp_n*64 + nt*8;
                if (lc >= ncols) break;
                int m = mc + lc + tp;
                float bi0 = __ldg(&bi[m]), bi1 = __ldg(&bi[m+1]);
                float s0 = 0.f, s1 = 0.f, t0 = 0.f, t1 = 0.f;
                if (sl >= 0) {
                    s0 = __ldg(&d_bns[sl*384 + m]); s1 = __ldg(&d_bns[sl*384 + m+1]);
                    t0 = __ldg(&d_bnt[sl*384 + m]); t1 = __ldg(&d_bnt[sl*384 + m+1]);
                }
                #pragma unroll
                for (int h = 0; h < 2; h++) {
                    int pt = warp_m*16 + h*8 + g;
                    float x0 = acc[nt][2*h]   + bi0;
                    float x1 = acc[nt][2*h+1] + bi1;
                    if (sl >= 0) {
                        x0 = fmaxf(fmaf(x0, s0, t0), 0.f);
                        x1 = fmaxf(fmaf(x1, s1, t1), 0.f);
                    }
                    *(__half2*)(dstP + (size_t)(pt*dstr + dco[l] + m)*2) =
                        __floats2half2_rn(x0, x1);
                }
            }
        }
        __syncthreads();
    }

    // ---- heads: fp in A (dh3), s in B (sh1); 8 pts per warp ----
    float4 wv = *(const float4*)&sh2w[lane*4];
    float sb = __ldg(sh2b);
    #pragma unroll
    for (int i = 0; i < 8; i++) {
        int p = wid*8 + i, ptg = rowbase + p;
        uint2 su = *(const uint2*)(Bbuf + (size_t)(p*BSTR2 + lane*4)*2);
        __half2 s0 = *(__half2*)&su.x, s1 = *(__half2*)&su.y;
        float sacc = __low2float(s0)*wv.x + __high2float(s0)*wv.y
                   + __low2float(s1)*wv.z + __high2float(s1)*wv.w;
        uint2 fu = *(const uint2*)(Abuf + (size_t)(p*ASTR2 + lane*4)*2);
        __half2 f0 = *(__half2*)&fu.x, f1 = *(__half2*)&fu.y;
        float v0 = __low2float(f0), v1 = __high2float(f0);
        float v2 = __low2float(f1), v3 = __high2float(f1);
        float ss = v0*v0 + v1*v1 + v2*v2 + v3*v3;
        #pragma unroll
        for (int o = 16; o > 0; o >>= 1) {
            sacc += __shfl_xor_sync(0xffffffff, sacc, o);
            ss   += __shfl_xor_sync(0xffffffff, ss, o);
        }
        if (lane == 0) outScore[ptg] = 1.f / (1.f + expf(-(sacc + sb)));
        float inv = 1.f / fmaxf(sqrtf(ss), 1e-12f);
        *(float4*)&outVf[(size_t)ptg*128 + lane*4] =
            make_float4(v0*inv, v1*inv, v2*inv, v3*inv);
    }
}

extern "C" void kernel_launch(void* const* d_in, const int* in_sizes, int n_in,
                              void* d_out, int out_size) {
    const float* pcd_xyz = (const float*)d_in[0];
    const float* rgb_xyz = (const float*)d_in[1];
    const float* pcd_f   = (const float*)d_in[2];
    const float* rgb_f   = (const float*)d_in[3];
    const float* cc1_w = (const float*)d_in[4];  const float* cc1_b = (const float*)d_in[5];
    const float* cc_bn = (const float*)d_in[6];
    const float* cc2_w = (const float*)d_in[7];  const float* cc2_b = (const float*)d_in[8];
    const float* co1_w = (const float*)d_in[9];  const float* co1_b = (const float*)d_in[10];
    const float* co_bn = (const float*)d_in[11];
    const float* co2_w = (const float*)d_in[12]; const float* co2_b = (const float*)d_in[13];
    const float* dh1_w = (const float*)d_in[14]; const float* dh1_b = (const float*)d_in[15];
    const float* dh1_bn= (const float*)d_in[16];
    const float* dh2_w = (const float*)d_in[17]; const float* dh2_b = (const float*)d_in[18];
    const float* dh2_bn= (const float*)d_in[19];
    const float* dh3_w = (const float*)d_in[20]; const float* dh3_b = (const float*)d_in[21];
    const float* sh1_w = (const float*)d_in[22]; const float* sh1_b = (const float*)d_in[23];
    const float* sh_bn = (const float*)d_in[24];
    const float* sh2_w = (const float*)d_in[25]; const float* sh2_b = (const float*)d_in[26];
    float* out = (float*)d_out;

    unsigned short *hw, *ut, *rgbt;
    cudaGetSymbolAddress((void**)&hw, d_hw);
    cudaGetSymbolAddress((void**)&ut, d_u);
    cudaGetSymbolAddress((void**)&rgbt, d_rgbt);
    cudaFuncSetAttribute(k_ug,   cudaFuncAttributeMaxDynamicSharedMemorySize, 2*UG_STAGE);
    cudaFuncSetAttribute(k_mega, cudaFuncAttributeMaxDynamicSharedMemorySize, SMEM2);

    // weight segment table
    WSegG ws;
    // cc1 split into 3 k-blocks, packed as big [128][1152] k-major
    for (int k = 0; k < 3; k++) {
        ws.s[k] = cc1_w; ws.M[k] = 384; ws.K[k] = 128; ws.off[k] = 0;
        ws.dstM[k] = 1152; ws.dstOff[k] = k*384; ws.srcLd[k] = 384; ws.srcCoff[k] = k*128;
    }
    const float* srcs[7] = {cc2_w, co1_w, co2_w, dh1_w, dh2_w, dh3_w, sh1_w};
    int Ms7[7]   = {128, 256, 128, 160, 160, 128, 128};
    int Ks7[7]   = {384, 256, 256, 160, 160, 160, 128};
    int offs7[7] = {147456, 196608, 262144, 294912, 320512, 346112, 366592};
    for (int i = 0; i < 7; i++) {
        int j = 3 + i;
        ws.s[j] = srcs[i]; ws.M[j] = Ms7[i]; ws.K[j] = Ks7[i]; ws.off[j] = offs7[i];
        ws.dstM[j] = Ms7[i]; ws.dstOff[j] = 0; ws.srcLd[j] = Ks7[i]; ws.srcCoff[j] = 0;
    }

    LBias lb;
    lb.b[0] = cc2_b; lb.b[1] = co1_b; lb.b[2] = co2_b;
    lb.b[3] = dh1_b; lb.b[4] = dh2_b; lb.b[5] = dh3_b; lb.b[6] = sh1_b;

    // ---- prep ----
    k_clear<<<(NCELL+255)/256, 256>>>();
    k_build<<<(NR+255)/256, 256>>>(rgb_xyz);
    k_3nn<<<(NP+127)/128, 128>>>(pcd_xyz);
    k_trans16<<<dim3(NR/32, 4), dim3(32,8)>>>(rgb_f);
    k_bnprep5<<<5, 384>>>(cc_bn, co_bn, dh1_bn, dh2_bn, sh_bn);
    k_wcvt<<<(382976+255)/256, 256>>>(ws);
    cudaMemcpyAsync(out, pcd_xyz, (size_t)NP*3*sizeof(float), cudaMemcpyDeviceToDevice);

    // ---- u table: [8192][1152] = rgb_f . [W0|W1|W2]^T ----
    k_ug<<<dim3(NR/128, 9), 256, 2*UG_STAGE>>>((const __half*)rgbt, (const __half*)hw,
                                               (__half*)ut);

    // ---- fused chain (64-pt tiles, 2 CTAs/SM) ----
    k_mega<<<NP/64, 256, SMEM2>>>(pcd_f, (const __half*)hw, lb, cc1_b,
                                  sh2_w, sh2_b,
                                  out + (size_t)NP*3, out + (size_t)NP*4);
}